// round 3
// baseline (speedup 1.0000x reference)
#include <cuda_runtime.h>
#include <cstdint>
#include <cstddef>

#define BB 8
#define NN 4096
#define MM 1024
#define DD 64
#define PTS 16
#define NPAIR 8
#define FPS_THREADS 256   /* NN / PTS */
#define NWARP 8
#define P2T 256
#define OUT_COLS 134      /* D + 3 + D + 3 */
#define COPY_BLOCKS 64
#define TAIL_BLOCKS 8
#define ROWS_PER_COPY ((BB * NN) / COPY_BLOCKS)  /* 512 */

// ---------------- scratch (no allocations allowed) ----------------
__device__ int   g_sidx[BB * MM];   // global index of sampled points
__device__ float g_lrx[BB * MM];    // sampled positions, SoA
__device__ float g_lry[BB * MM];
__device__ float g_lrz[BB * MM];

// ---------------- packed f32x2 helpers (bit-exact per-lane .rn ops) ------
__device__ __forceinline__ unsigned long long packf2(float lo, float hi) {
    unsigned long long r;
    asm("mov.b64 %0, {%1, %2};" : "=l"(r) : "f"(lo), "f"(hi));
    return r;
}
__device__ __forceinline__ void unpackf2(unsigned long long v, float& lo, float& hi) {
    asm("mov.b64 {%0, %1}, %2;" : "=f"(lo), "=f"(hi) : "l"(v));
}
__device__ __forceinline__ unsigned long long addx2(unsigned long long a, unsigned long long b) {
    unsigned long long r;
    asm("add.rn.f32x2 %0, %1, %2;" : "=l"(r) : "l"(a), "l"(b));
    return r;
}
__device__ __forceinline__ unsigned long long mulx2(unsigned long long a, unsigned long long b) {
    unsigned long long r;
    asm("mul.rn.f32x2 %0, %1, %2;" : "=l"(r) : "l"(a), "l"(b));
    return r;
}
__device__ __forceinline__ unsigned redux_max_u32(unsigned v) {
    unsigned r;
    asm("redux.sync.max.u32 %0, %1, 0xffffffff;" : "=r"(r) : "r"(v));
    return r;
}

struct FpsShared {
    unsigned long long wkey[2][NWARP];           // double-buffered per-warp keys
    unsigned long long xs2[NN], ys2[NN], zs2[NN]; // coords duplicated as (v,v)
};

// ---------------- Kernel 1: FPS (blocks 0..7) + overlapped copy/zero/batch ------------
__global__ __launch_bounds__(FPS_THREADS, 1)
void fps_kernel(const float* __restrict__ x, const float* __restrict__ pos,
                float* __restrict__ out, long long out_size) {
    if (blockIdx.x >= BB) {
        const int cb = blockIdx.x - BB;
        if (cb < COPY_BLOCKS) {
            // out[:, 0:67] = [x | pos]  (independent of FPS -> runs concurrently)
            const int r0 = cb * ROWS_PER_COPY;
            for (int e = threadIdx.x; e < ROWS_PER_COPY * 67; e += FPS_THREADS) {
                int r = r0 + e / 67;
                int c = e - 67 * (e / 67);
                float v = (c < DD) ? x[(size_t)r * DD + c] : pos[3 * r + (c - DD)];
                out[(size_t)r * OUT_COLS + c] = v;
            }
        } else {
            // tuple tail outputs, if present in out buffer
            const long long outx = (long long)BB * NN * OUT_COLS;
            const long long zs = (long long)BB * NN * 3;
            const int gt = (cb - COPY_BLOCKS) * FPS_THREADS + threadIdx.x;
            if (out_size >= outx + zs)
                for (long long i = gt; i < zs; i += (long long)TAIL_BLOCKS * FPS_THREADS)
                    out[outx + i] = 0.0f;
            if (out_size >= outx + zs + (long long)BB * NN)
                for (int i = gt; i < BB * NN; i += TAIL_BLOCKS * FPS_THREADS)
                    out[outx + zs + i] = (float)(i >> 12);  // i / NN
        }
        return;
    }

    extern __shared__ unsigned char smraw[];
    FpsShared* sm = reinterpret_cast<FpsShared*>(smraw);
    const int b = blockIdx.x;
    const int t = threadIdx.x;
    const int warp = t >> 5;
    const int lane = t & 31;
    const float* posb = pos + (size_t)b * NN * 3;

    for (int i = t; i < NN; i += FPS_THREADS) {
        float X = posb[3 * i + 0], Y = posb[3 * i + 1], Z = posb[3 * i + 2];
        sm->xs2[i] = packf2(X, X);
        sm->ys2[i] = packf2(Y, Y);
        sm->zs2[i] = packf2(Z, Z);
    }
    __syncthreads();

    // Per-thread points, pre-negated and packed in pairs.
    unsigned long long npx[NPAIR], npy[NPAIR], npz[NPAIR];
    float mind[PTS];
    const int base = t * PTS;
#pragma unroll
    for (int p = 0; p < NPAIR; p++) {
        float a0, a1, d0, d1;
        unpackf2(sm->xs2[base + 2 * p], a0, d0);
        unpackf2(sm->xs2[base + 2 * p + 1], a1, d1);
        npx[p] = packf2(-a0, -a1);
        unpackf2(sm->ys2[base + 2 * p], a0, d0);
        unpackf2(sm->ys2[base + 2 * p + 1], a1, d1);
        npy[p] = packf2(-a0, -a1);
        unpackf2(sm->zs2[base + 2 * p], a0, d0);
        unpackf2(sm->zs2[base + 2 * p + 1], a1, d1);
        npz[p] = packf2(-a0, -a1);
    }
#pragma unroll
    for (int j = 0; j < PTS; j++) mind[j] = 3.402823466e+38f;  // finfo(float32).max

    unsigned long long lxx = sm->xs2[0], lyy = sm->ys2[0], lzz = sm->zs2[0];
    if (t == 0) {
        float wx, wy, wz, dum;
        unpackf2(lxx, wx, dum); unpackf2(lyy, wy, dum); unpackf2(lzz, wz, dum);
        g_sidx[b * MM] = b * NN;
        g_lrx[b * MM] = wx; g_lry[b * MM] = wy; g_lrz[b * MM] = wz;
    }
    const unsigned nbase = ~(unsigned)base;

    for (int step = 1; step < MM; ++step) {
        // Distances: dx = lx + (-px) == lx - px; squares identical to (px-lx)^2.
#pragma unroll
        for (int p = 0; p < NPAIR; p++) {
            unsigned long long dx = addx2(lxx, npx[p]);
            unsigned long long dy = addx2(lyy, npy[p]);
            unsigned long long dz = addx2(lzz, npz[p]);
            unsigned long long s  = addx2(addx2(mulx2(dx, dx), mulx2(dy, dy)),
                                          mulx2(dz, dz));
            float d0, d1;
            unpackf2(s, d0, d1);
            mind[2 * p]     = fminf(mind[2 * p], d0);
            mind[2 * p + 1] = fminf(mind[2 * p + 1], d1);
        }

        // In-thread argmax tree over 16 leaves, constant-index selects at level 1;
        // lower index wins ties (first-occurrence semantics).
        float v[NPAIR]; int id[NPAIR];
#pragma unroll
        for (int k = 0; k < NPAIR; k++) {
            bool keep = mind[2 * k] >= mind[2 * k + 1];
            v[k]  = keep ? mind[2 * k] : mind[2 * k + 1];
            id[k] = keep ? (2 * k) : (2 * k + 1);
        }
#pragma unroll
        for (int s = 1; s < NPAIR; s <<= 1) {
#pragma unroll
            for (int j = 0; j < NPAIR; j += 2 * s) {
                bool keep = v[j] >= v[j + s];
                v[j]  = keep ? v[j]  : v[j + s];
                id[j] = keep ? id[j] : id[j + s];
            }
        }

        // Warp argmax: max value bits, then max ~(global idx) among maxima.
        unsigned vb = __float_as_uint(v[0]);
        unsigned vmax = redux_max_u32(vb);
        unsigned cand = (vb == vmax) ? (nbase - (unsigned)id[0]) : 0u;  // = ~(base+id)
        unsigned imax = redux_max_u32(cand);
        if (lane == 0)
            sm->wkey[step & 1][warp] =
                ((unsigned long long)vmax << 32) | (unsigned long long)imax;
        __syncthreads();

        // Cross-warp: each lane grabs one warp key, two redux combine them.
        unsigned long long k = sm->wkey[step & 1][lane & (NWARP - 1)];
        unsigned hi = (unsigned)(k >> 32), lo = (unsigned)k;
        unsigned gv = redux_max_u32(hi);
        unsigned gc = (hi == gv) ? lo : 0u;
        unsigned gi = redux_max_u32(gc);
        unsigned widx = ~gi;

        lxx = sm->xs2[widx]; lyy = sm->ys2[widx]; lzz = sm->zs2[widx];
        if (t == 0) {
            float wx, wy, wz, dum;
            unpackf2(lxx, wx, dum); unpackf2(lyy, wy, dum); unpackf2(lzz, wz, dum);
            g_sidx[b * MM + step] = b * NN + (int)widx;
            g_lrx[b * MM + step] = wx;
            g_lry[b * MM + step] = wy;
            g_lrz[b * MM + step] = wz;
        }
    }
}

// ---------------- Kernel 2: 1-NN over sampled points + gather of cols 67..133 ----------
__global__ __launch_bounds__(P2T)
void knn_out_kernel(const float* __restrict__ x, const float* __restrict__ pos,
                    float* __restrict__ out) {
    __shared__ unsigned long long nlx[MM / 2], nly[MM / 2], nlz[MM / 2];
    __shared__ int gsrc[P2T];

    const int b = blockIdx.y;
    const float2* fx = (const float2*)(g_lrx) + b * (MM / 2);
    const float2* fy = (const float2*)(g_lry) + b * (MM / 2);
    const float2* fz = (const float2*)(g_lrz) + b * (MM / 2);
    for (int i = threadIdx.x; i < MM / 2; i += P2T) {
        float2 a = fx[i]; nlx[i] = packf2(-a.x, -a.y);
        float2 c = fy[i]; nly[i] = packf2(-c.x, -c.y);
        float2 e = fz[i]; nlz[i] = packf2(-e.x, -e.y);
    }
    __syncthreads();

    const int rlocal = blockIdx.x * P2T + threadIdx.x;
    const int row = b * NN + rlocal;
    const float ax = pos[3 * row + 0];
    const float ay = pos[3 * row + 1];
    const float az = pos[3 * row + 2];
    const unsigned long long axx = packf2(ax, ax);
    const unsigned long long ayy = packf2(ay, ay);
    const unsigned long long azz = packf2(az, az);

    float bv0 = 3.4e+38f, bv1 = 3.4e+38f, bv2 = 3.4e+38f, bv3 = 3.4e+38f;
    int bi0 = 0, bi1 = 1, bi2 = 2, bi3 = 3;
    for (int j = 0; j < MM; j += 4) {
        int p = j >> 1;
        unsigned long long dxA = addx2(axx, nlx[p]);
        unsigned long long dyA = addx2(ayy, nly[p]);
        unsigned long long dzA = addx2(azz, nlz[p]);
        unsigned long long sA  = addx2(addx2(mulx2(dxA, dxA), mulx2(dyA, dyA)),
                                       mulx2(dzA, dzA));
        unsigned long long dxB = addx2(axx, nlx[p + 1]);
        unsigned long long dyB = addx2(ayy, nly[p + 1]);
        unsigned long long dzB = addx2(azz, nlz[p + 1]);
        unsigned long long sB  = addx2(addx2(mulx2(dxB, dxB), mulx2(dyB, dyB)),
                                       mulx2(dzB, dzB));
        float d0, d1, d2, d3;
        unpackf2(sA, d0, d1);
        unpackf2(sB, d2, d3);
        if (d0 < bv0) { bv0 = d0; bi0 = j + 0; }
        if (d1 < bv1) { bv1 = d1; bi1 = j + 1; }
        if (d2 < bv2) { bv2 = d2; bi2 = j + 2; }
        if (d3 < bv3) { bv3 = d3; bi3 = j + 3; }
    }
    bool t1 = (bv1 < bv0) || (bv1 == bv0 && bi1 < bi0);
    float va = t1 ? bv1 : bv0;  int ia = t1 ? bi1 : bi0;
    bool t2 = (bv3 < bv2) || (bv3 == bv2 && bi3 < bi2);
    float vb = t2 ? bv3 : bv2;  int ib = t2 ? bi3 : bi2;
    bool t3 = (vb < va) || (vb == va && ib < ia);
    int bi = t3 ? ib : ia;

    gsrc[threadIdx.x] = g_sidx[b * MM + bi];
    __syncthreads();

    // Write only cols 67..133: [x[g] | pos[g]] per row, cooperative + coalesced.
    const long long rowbase = (long long)b * NN + (long long)blockIdx.x * P2T;
    for (int e = threadIdx.x; e < P2T * 67; e += P2T) {
        int r = e / 67;
        int c = e - 67 * r;
        int g = gsrc[r];
        float val = (c < DD) ? x[(size_t)g * DD + c] : pos[3 * g + (c - DD)];
        out[((size_t)rowbase + r) * OUT_COLS + 67 + c] = val;
    }
}

extern "C" void kernel_launch(void* const* d_in, const int* in_sizes, int n_in,
                              void* d_out, int out_size) {
    const float* x   = (const float*)d_in[0];
    const float* pos = (const float*)d_in[1];
    float* out = (float*)d_out;

    cudaFuncSetAttribute(fps_kernel, cudaFuncAttributeMaxDynamicSharedMemorySize,
                         (int)sizeof(FpsShared));
    fps_kernel<<<BB + COPY_BLOCKS + TAIL_BLOCKS, FPS_THREADS, sizeof(FpsShared)>>>(
        x, pos, out, (long long)out_size);
    knn_out_kernel<<<dim3(NN / P2T, BB), P2T>>>(x, pos, out);
}